// round 10
// baseline (speedup 1.0000x reference)
#include <cuda_runtime.h>
#include <math.h>

#define TT 2048
#define HH 1024
#define II 1024
#define NE 16
#define KTOP 4
#define EPSF 1e-5f
#define ALPHAF 1.702f
#define LIMITF 7.0f

#define BM 128
#define BN 256
#define BK 16
#define PAD 20
#define NSTG 4
#define STG_A_BYTES (BM * PAD * 4)            // 10240
#define STG_B_BYTES (BN * PAD * 4)            // 20480
#define B_REGION (NSTG * STG_A_BYTES)         // 40960
#define SMEM_BYTES (NSTG * (STG_A_BYTES + STG_B_BYTES))   // 122880

// ---------------- scratch (static device globals; no allocation) -------------
__device__ __align__(16) float g_t[TT * HH];            // tf32-rounded rmsnorm out
__device__ __align__(16) float g_s[TT * KTOP * II];     // tf32-rounded swiglu out
__device__ __align__(16) float g_y[TT * KTOP * HH];
__device__ __align__(16) float g_w1r[NE * II * HH];     // tf32-rounded even w1 rows (67MB)
__device__ __align__(16) float g_w2r[NE * HH * II];     // tf32-rounded w2 (67MB)
__device__ float g_slot_w[TT * KTOP];
__device__ int   g_expert_cnt[NE];
__device__ int   g_expert_slots[NE * TT];

// ---------------- helpers ------------------------------------------------------
__device__ __forceinline__ unsigned f2tf(float f) {
    unsigned r;
    asm("cvt.rna.tf32.f32 %0, %1;" : "=r"(r) : "f"(f));
    return r;
}

__device__ __forceinline__ void mma_tf32(float* d, const unsigned* a, const unsigned* b) {
    asm volatile(
        "mma.sync.aligned.m16n8k8.row.col.f32.tf32.tf32.f32 "
        "{%0,%1,%2,%3}, {%4,%5,%6,%7}, {%8,%9}, {%0,%1,%2,%3};"
        : "+f"(d[0]), "+f"(d[1]), "+f"(d[2]), "+f"(d[3])
        : "r"(a[0]), "r"(a[1]), "r"(a[2]), "r"(a[3]), "r"(b[0]), "r"(b[1]));
}

__device__ __forceinline__ void ldsm4(unsigned* r, unsigned addr) {
    asm volatile("ldmatrix.sync.aligned.m8n8.x4.shared.b16 {%0,%1,%2,%3}, [%4];"
        : "=r"(r[0]), "=r"(r[1]), "=r"(r[2]), "=r"(r[3]) : "r"(addr));
}

__device__ __forceinline__ void cp16(unsigned dst, const void* src) {
    asm volatile("cp.async.cg.shared.global [%0], [%1], 16;" :: "r"(dst), "l"(src));
}
#define CP_COMMIT() asm volatile("cp.async.commit_group;")
#define CP_WAIT2()  asm volatile("cp.async.wait_group 2;")

// ---------------- kernel 0 -----------------------------------------------------
__global__ void zero_cnt_kernel() {
    if (threadIdx.x < NE) g_expert_cnt[threadIdx.x] = 0;
}

// ---------------- prep: round weights to tf32 scratch --------------------------
// w1 even rows: g_w1r[e][n][h] = rna(w1[e][2n][h])
__global__ void prep_w1_kernel(const float* __restrict__ w1) {
    int idx = blockIdx.x * 256 + threadIdx.x;     // float4 index
    int r = idx >> 8;                              // global row in [0, NE*II)
    int q = idx & 255;
    int e = r >> 10, n = r & 1023;
    float4 v = *((const float4*)(w1 + ((size_t)e * 2 * II + 2 * n) * HH) + q);
    uint4 u;
    u.x = f2tf(v.x); u.y = f2tf(v.y); u.z = f2tf(v.z); u.w = f2tf(v.w);
    *((uint4*)(g_w1r + (size_t)r * HH) + q) = u;
}

__global__ void prep_w2_kernel(const float* __restrict__ w2) {
    size_t idx = (size_t)blockIdx.x * 256 + threadIdx.x;  // float4 index
    float4 v = *((const float4*)w2 + idx);
    uint4 u;
    u.x = f2tf(v.x); u.y = f2tf(v.y); u.z = f2tf(v.z); u.w = f2tf(v.w);
    *((uint4*)g_w2r + idx) = u;
}

// ---------------- kernel 1: fused RMSNorm + gate + top4 + routing -------------
__global__ void norm_gate_kernel(const float* __restrict__ x,
                                 const float* __restrict__ scale,
                                 const float* __restrict__ gate_w,
                                 const float* __restrict__ gate_b) {
    int t = blockIdx.x;
    int tid = threadIdx.x;
    __shared__ float ts[HH];
    __shared__ float gv[NE];
    __shared__ float red[8];

    float4 v = *((const float4*)(x + (size_t)t * HH) + tid);
    float ss = v.x * v.x + v.y * v.y + v.z * v.z + v.w * v.w;
    #pragma unroll
    for (int o = 16; o; o >>= 1) ss += __shfl_xor_sync(0xffffffffu, ss, o);
    if ((tid & 31) == 0) red[tid >> 5] = ss;
    __syncthreads();
    if (tid < 8) {
        float s2 = red[tid];
        #pragma unroll
        for (int o = 4; o; o >>= 1) s2 += __shfl_xor_sync(0xffu, s2, o);
        if (tid == 0) red[0] = s2;
    }
    __syncthreads();
    float rms = rsqrtf(red[0] * (1.0f / HH) + EPSF);
    float4 sc = *((const float4*)scale + tid);
    float4 tv;
    tv.x = v.x * rms * sc.x; tv.y = v.y * rms * sc.y;
    tv.z = v.z * rms * sc.z; tv.w = v.w * rms * sc.w;
    *((float4*)ts + tid) = tv;
    uint4 u;
    u.x = f2tf(tv.x); u.y = f2tf(tv.y); u.z = f2tf(tv.z); u.w = f2tf(tv.w);
    *((uint4*)(g_t + (size_t)t * HH) + tid) = u;
    __syncthreads();

    int g = tid >> 4;
    int j = tid & 15;
    const float* wr = gate_w + g * HH;
    float sum = 0.f;
    for (int h = j; h < HH; h += 16) sum += ts[h] * wr[h];
    #pragma unroll
    for (int o = 8; o; o >>= 1) sum += __shfl_xor_sync(0xffffffffu, sum, o);
    if (j == 0) gv[g] = sum + gate_b[g];
    __syncthreads();

    if (tid == 0) {
        float vals[KTOP];
        int   idx[KTOP];
        bool  used[NE];
        #pragma unroll
        for (int e = 0; e < NE; e++) used[e] = false;
        #pragma unroll
        for (int k = 0; k < KTOP; k++) {
            float best = -INFINITY; int bi = 0;
            for (int e = 0; e < NE; e++)
                if (!used[e] && gv[e] > best) { best = gv[e]; bi = e; }
            used[bi] = true; vals[k] = best; idx[k] = bi;
        }
        float m = vals[0];
        float se = 0.f, w[KTOP];
        #pragma unroll
        for (int k = 0; k < KTOP; k++) { w[k] = __expf(vals[k] - m); se += w[k]; }
        float inv = 1.0f / se;
        #pragma unroll
        for (int k = 0; k < KTOP; k++) {
            int slot = t * KTOP + k;
            g_slot_w[slot] = w[k] * inv;
            int pos = atomicAdd(&g_expert_cnt[idx[k]], 1);
            g_expert_slots[idx[k] * TT + pos] = slot;
        }
    }
}

// ================= tf32 mma.sync GEMMs =========================================
// 128x256 block tile, 8 warps (2m x 4n), 64x64 warp tile, ldmatrix frags.
// BOTH operands pure cp.async from pre-rounded tf32 sources; 4-stage pipeline.

// ---------------- mlp1: GEMM1 (pre-gathered even w1 rows) + bias + swiglu -----
__global__ void __launch_bounds__(256, 1) mlp1_kernel(const float* __restrict__ b1) {
    int e = blockIdx.z;
    int cnt = g_expert_cnt[e];
    int mt = blockIdx.x;
    if (mt * BM >= cnt) return;
    int ntB = blockIdx.y * BN;

    extern __shared__ __align__(16) char dsm[];
    unsigned smb;
    asm("{ .reg .u64 t; cvta.to.shared.u64 t, %1; cvt.u32.u64 %0, t; }" : "=r"(smb) : "l"(dsm));
    __shared__ int slots[BM];

    int tid = threadIdx.x;
    if (tid < BM) {
        int idx = mt * BM + tid;
        slots[tid] = (idx < cnt) ? g_expert_slots[e * TT + idx] : -1;
    }
    __syncthreads();

    int lane = tid & 31, wid = tid >> 5;
    int wm = wid & 1, wn = wid >> 1;          // 2 x 4 warps
    int grp = lane >> 2, tig = lane & 3;
    int rA = (lane & 7) + (((lane >> 3) & 1) << 3);
    int kA = (lane >> 4) << 2;
    int rB = (lane & 7) + ((lane >> 4) << 3);
    int kB = ((lane >> 3) & 1) << 2;
    unsigned aFrag = smb + (unsigned)(((wm * 64 + rA) * PAD + kA) * 4);
    unsigned bFrag = smb + B_REGION + (unsigned)(((wn * 64 + rB) * PAD + kB) * 4);

    // staging: A rows sr, sr+64 (2 cp16); B rows sr+{0,64,128,192} (4 cp16)
    int sr = tid >> 2;
    int kq = (tid & 3) * 4;
    const float* w1e = g_w1r + (size_t)e * II * HH;
    const float* aptr[2];
    const float* bptr[4];
    #pragma unroll
    for (int i = 0; i < 2; i++) {
        int s = slots[sr + 64 * i];
        aptr[i] = g_t + (size_t)((s >= 0) ? (s >> 2) : 0) * HH + kq;
    }
    #pragma unroll
    for (int i = 0; i < 4; i++)
        bptr[i] = w1e + (size_t)(ntB + sr + 64 * i) * HH + kq;
    unsigned aDst = smb + (unsigned)((sr * PAD + kq) * 4);
    unsigned bDst = smb + B_REGION + (unsigned)((sr * PAD + kq) * 4);

    float acc[4][8][4] = {};

    // prologue: stages 0..2
    #pragma unroll
    for (int c = 0; c < NSTG - 1; c++) {
        #pragma unroll
        for (int i = 0; i < 2; i++)
            cp16(aDst + c * STG_A_BYTES + i * (64 * PAD * 4), aptr[i] + c * BK);
        #pragma unroll
        for (int i = 0; i < 4; i++)
            cp16(bDst + c * STG_B_BYTES + i * (64 * PAD * 4), bptr[i] + c * BK);
        CP_COMMIT();
    }

    const int NKT = HH / BK;   // 64
    #pragma unroll 2
    for (int kb = 0; kb < NKT; kb++) {
        int cur = kb & (NSTG - 1);
        CP_WAIT2();
        __syncthreads();
        int kf = kb + NSTG - 1;
        if (kf < NKT) {
            int st = kf & (NSTG - 1);
            #pragma unroll
            for (int i = 0; i < 2; i++)
                cp16(aDst + st * STG_A_BYTES + i * (64 * PAD * 4), aptr[i] + kf * BK);
            #pragma unroll
            for (int i = 0; i < 4; i++)
                cp16(bDst + st * STG_B_BYTES + i * (64 * PAD * 4), bptr[i] + kf * BK);
        }
        CP_COMMIT();
        unsigned aOff = aFrag + (unsigned)(cur * STG_A_BYTES);
        unsigned bOff = bFrag + (unsigned)(cur * STG_B_BYTES);
        #pragma unroll
        for (int ks = 0; ks < 2; ks++) {
            unsigned afr[4][4], bfr[4][4];
            #pragma unroll
            for (int sm = 0; sm < 4; sm++)
                ldsm4(afr[sm], aOff + (unsigned)((sm * 16 * PAD + ks * 8) * 4));
            #pragma unroll
            for (int p = 0; p < 4; p++)
                ldsm4(bfr[p], bOff + (unsigned)((p * 16 * PAD + ks * 8) * 4));
            #pragma unroll
            for (int sm = 0; sm < 4; sm++)
                #pragma unroll
                for (int sn = 0; sn < 8; sn++)
                    mma_tf32(acc[sm][sn], afr[sm], &bfr[sn >> 1][(sn & 1) * 2]);
        }
    }

    const float* b1e = b1 + e * (2 * II);
    #pragma unroll
    for (int sm = 0; sm < 4; sm++) {
        int rbase = wm * 64 + sm * 16 + grp;
        #pragma unroll
        for (int half = 0; half < 2; half++) {
            int row = rbase + half * 8;
            int slot = slots[row];
            if (slot < 0) continue;
            float* srow = g_s + (size_t)slot * II;
            #pragma unroll
            for (int sn = 0; sn < 8; sn++) {
                int n = ntB + wn * 64 + sn * 8 + 2 * tig;
                #pragma unroll
                for (int cc = 0; cc < 2; cc++) {
                    float hsum = acc[sm][sn][half * 2 + cc] + b1e[2 * (n + cc)];
                    float gl = fminf(hsum, LIMITF);
                    float sig = 1.0f / (1.0f + __expf(-ALPHAF * gl));
                    srow[n + cc] = __uint_as_float(f2tf(gl * sig * (LIMITF + 1.0f)));
                }
            }
        }
    }
}

// ---------------- mlp2: GEMM2 + bias, scaled by routing weight ----------------
__global__ void __launch_bounds__(256, 1) mlp2_kernel(const float* __restrict__ b2) {
    int e = blockIdx.z;
    int cnt = g_expert_cnt[e];
    int mt = blockIdx.x;
    if (mt * BM >= cnt) return;
    int ntB = blockIdx.y * BN;

    extern __shared__ __align__(16) char dsm[];
    unsigned smb;
    asm("{ .reg .u64 t; cvta.to.shared.u64 t, %1; cvt.u32.u64 %0, t; }" : "=r"(smb) : "l"(dsm));
    __shared__ int slots[BM];

    int tid = threadIdx.x;
    if (tid < BM) {
        int idx = mt * BM + tid;
        slots[tid] = (idx < cnt) ? g_expert_slots[e * TT + idx] : -1;
    }
    __syncthreads();

    int lane = tid & 31, wid = tid >> 5;
    int wm = wid & 1, wn = wid >> 1;
    int grp = lane >> 2, tig = lane & 3;
    int rA = (lane & 7) + (((lane >> 3) & 1) << 3);
    int kA = (lane >> 4) << 2;
    int rB = (lane & 7) + ((lane >> 4) << 3);
    int kB = ((lane >> 3) & 1) << 2;
    unsigned aFrag = smb + (unsigned)(((wm * 64 + rA) * PAD + kA) * 4);
    unsigned bFrag = smb + B_REGION + (unsigned)(((wn * 64 + rB) * PAD + kB) * 4);

    int sr = tid >> 2;
    int kq = (tid & 3) * 4;
    const float* w2e = g_w2r + (size_t)e * HH * II;
    const float* aptr[2];
    const float* bptr[4];
    #pragma unroll
    for (int i = 0; i < 2; i++) {
        int s = slots[sr + 64 * i];
        aptr[i] = g_s + (size_t)((s >= 0) ? s : 0) * II + kq;
    }
    #pragma unroll
    for (int i = 0; i < 4; i++)
        bptr[i] = w2e + (size_t)(ntB + sr + 64 * i) * II + kq;
    unsigned aDst = smb + (unsigned)((sr * PAD + kq) * 4);
    unsigned bDst = smb + B_REGION + (unsigned)((sr * PAD + kq) * 4);

    float acc[4][8][4] = {};

    #pragma unroll
    for (int c = 0; c < NSTG - 1; c++) {
        #pragma unroll
        for (int i = 0; i < 2; i++)
            cp16(aDst + c * STG_A_BYTES + i * (64 * PAD * 4), aptr[i] + c * BK);
        #pragma unroll
        for (int i = 0; i < 4; i++)
            cp16(bDst + c * STG_B_BYTES + i * (64 * PAD * 4), bptr[i] + c * BK);
        CP_COMMIT();
    }

    const int NKT = II / BK;
    #pragma unroll 2
    for (int kb = 0; kb < NKT; kb++) {
        int cur = kb & (NSTG - 1);
        CP_WAIT2();
        __syncthreads();
        int kf = kb + NSTG - 1;
        if (kf < NKT) {
            int st = kf & (NSTG - 1);
            #pragma unroll
            for (int i = 0; i < 2; i++)
                cp16(aDst + st * STG_A_BYTES + i * (64 * PAD * 4), aptr[i] + kf * BK);
            #pragma unroll
            for (int i = 0; i < 4; i++)
                cp16(bDst + st * STG_B_BYTES + i * (64 * PAD * 4), bptr[i] + kf * BK);
        }
        CP_COMMIT();
        unsigned aOff = aFrag + (unsigned)(cur * STG_A_BYTES);
        unsigned bOff = bFrag + (unsigned)(cur * STG_B_BYTES);
        #pragma unroll
        for (int ks = 0; ks < 2; ks++) {
            unsigned afr[4][4], bfr[4][4];
            #pragma unroll
            for (int sm = 0; sm < 4; sm++)
                ldsm4(afr[sm], aOff + (unsigned)((sm * 16 * PAD + ks * 8) * 4));
            #pragma unroll
            for (int p = 0; p < 4; p++)
                ldsm4(bfr[p], bOff + (unsigned)((p * 16 * PAD + ks * 8) * 4));
            #pragma unroll
            for (int sm = 0; sm < 4; sm++)
                #pragma unroll
                for (int sn = 0; sn < 8; sn++)
                    mma_tf32(acc[sm][sn], afr[sm], &bfr[sn >> 1][(sn & 1) * 2]);
        }
    }

    const float* b2e = b2 + e * HH;
    #pragma unroll
    for (int sm = 0; sm < 4; sm++) {
        int rbase = wm * 64 + sm * 16 + grp;
        #pragma unroll
        for (int half = 0; half < 2; half++) {
            int row = rbase + half * 8;
            int slot = slots[row];
            if (slot < 0) continue;
            float rw = g_slot_w[slot];
            float* yrow = g_y + (size_t)slot * HH;
            #pragma unroll
            for (int sn = 0; sn < 8; sn++) {
                int n = ntB + wn * 64 + sn * 8 + 2 * tig;
                #pragma unroll
                for (int cc = 0; cc < 2; cc++)
                    yrow[n + cc] = (acc[sm][sn][half * 2 + cc] + b2e[n + cc]) * rw;
            }
        }
    }
}

// ---------------- finalize: out = x + sum_k y[t*4+k] --------------------------
__global__ void finalize_kernel(const float* __restrict__ x,
                                float* __restrict__ out) {
    int qi = blockIdx.x * 256 + threadIdx.x;
    int t = qi >> 8;
    int h4 = qi & 255;
    float4 v = *((const float4*)x + qi);
    const float4* yb = (const float4*)(g_y + (size_t)t * KTOP * HH) + h4;
    float4 a = yb[0], b = yb[256], c = yb[512], d = yb[768];
    v.x += a.x + b.x + c.x + d.x;
    v.y += a.y + b.y + c.y + d.y;
    v.z += a.z + b.z + c.z + d.z;
    v.w += a.w + b.w + c.w + d.w;
    *((float4*)out + qi) = v;
}

// ---------------- launcher -----------------------------------------------------
extern "C" void kernel_launch(void* const* d_in, const int* in_sizes, int n_in,
                              void* d_out, int out_size) {
    const float* x      = (const float*)d_in[0];
    const float* scale  = (const float*)d_in[1];
    const float* gate_w = (const float*)d_in[2];
    const float* gate_b = (const float*)d_in[3];
    const float* w1     = (const float*)d_in[4];
    const float* b1     = (const float*)d_in[5];
    const float* w2     = (const float*)d_in[6];
    const float* b2     = (const float*)d_in[7];
    float* out = (float*)d_out;

    cudaFuncSetAttribute(mlp1_kernel, cudaFuncAttributeMaxDynamicSharedMemorySize, SMEM_BYTES);
    cudaFuncSetAttribute(mlp2_kernel, cudaFuncAttributeMaxDynamicSharedMemorySize, SMEM_BYTES);

    zero_cnt_kernel<<<1, 32>>>();
    prep_w1_kernel<<<(NE * II * HH / 4) / 256, 256>>>(w1);
    prep_w2_kernel<<<(NE * HH * II / 4) / 256, 256>>>(w2);
    norm_gate_kernel<<<TT, 256>>>(x, scale, gate_w, gate_b);

    dim3 g1(TT / BM, II / BN, NE);    // (16, 4, 16)
    mlp1_kernel<<<g1, 256, SMEM_BYTES>>>(b1);

    dim3 g2(TT / BM, HH / BN, NE);
    mlp2_kernel<<<g2, 256, SMEM_BYTES>>>(b2);

    finalize_kernel<<<(TT * HH) / 1024, 256>>>(x, out);
}

// round 11
// speedup vs baseline: 1.0214x; 1.0214x over previous
#include <cuda_runtime.h>
#include <math.h>

#define TT 2048
#define HH 1024
#define II 1024
#define NE 16
#define KTOP 4
#define EPSF 1e-5f
#define ALPHAF 1.702f
#define LIMITF 7.0f

#define BM 128
#define BN 128
#define BK 16
#define PAD 20
#define NSTG 4
#define STG_A_BYTES (BM * PAD * 4)            // 10240
#define STG_B_BYTES (BN * PAD * 4)            // 10240
#define B_REGION (NSTG * STG_A_BYTES)         // 40960
#define SMEM_BYTES (NSTG * (STG_A_BYTES + STG_B_BYTES))   // 81920

// ---------------- scratch (static device globals; no allocation) -------------
__device__ __align__(16) float g_t[TT * HH];            // tf32-rounded rmsnorm out
__device__ __align__(16) float g_s[TT * KTOP * II];     // tf32-rounded swiglu out
__device__ __align__(16) float g_y[TT * KTOP * HH];
__device__ __align__(16) float g_w1r[NE * II * HH];     // tf32-rounded even w1 rows
__device__ __align__(16) float g_w2r[NE * HH * II];     // tf32-rounded w2
__device__ float g_slot_w[TT * KTOP];
__device__ int   g_expert_cnt[NE];
__device__ int   g_expert_slots[NE * TT];

// ---------------- helpers ------------------------------------------------------
__device__ __forceinline__ unsigned f2tf(float f) {
    unsigned r;
    asm("cvt.rna.tf32.f32 %0, %1;" : "=r"(r) : "f"(f));
    return r;
}

__device__ __forceinline__ void mma_tf32(float* d, const unsigned* a, const unsigned* b) {
    asm volatile(
        "mma.sync.aligned.m16n8k8.row.col.f32.tf32.tf32.f32 "
        "{%0,%1,%2,%3}, {%4,%5,%6,%7}, {%8,%9}, {%0,%1,%2,%3};"
        : "+f"(d[0]), "+f"(d[1]), "+f"(d[2]), "+f"(d[3])
        : "r"(a[0]), "r"(a[1]), "r"(a[2]), "r"(a[3]), "r"(b[0]), "r"(b[1]));
}

__device__ __forceinline__ void ldsm4(unsigned* r, unsigned addr) {
    asm volatile("ldmatrix.sync.aligned.m8n8.x4.shared.b16 {%0,%1,%2,%3}, [%4];"
        : "=r"(r[0]), "=r"(r[1]), "=r"(r[2]), "=r"(r[3]) : "r"(addr));
}

__device__ __forceinline__ void cp16(unsigned dst, const void* src) {
    asm volatile("cp.async.cg.shared.global [%0], [%1], 16;" :: "r"(dst), "l"(src));
}
#define CP_COMMIT() asm volatile("cp.async.commit_group;")
#define CP_WAIT2()  asm volatile("cp.async.wait_group 2;")

// ---------------- kernel 0 -----------------------------------------------------
__global__ void zero_cnt_kernel() {
    if (threadIdx.x < NE) g_expert_cnt[threadIdx.x] = 0;
}

// ---------------- prep: round weights to tf32 scratch --------------------------
__global__ void prep_w1_kernel(const float* __restrict__ w1) {
    int idx = blockIdx.x * 256 + threadIdx.x;     // float4 index
    int r = idx >> 8;                              // global row in [0, NE*II)
    int q = idx & 255;
    int e = r >> 10, n = r & 1023;
    float4 v = *((const float4*)(w1 + ((size_t)e * 2 * II + 2 * n) * HH) + q);
    uint4 u;
    u.x = f2tf(v.x); u.y = f2tf(v.y); u.z = f2tf(v.z); u.w = f2tf(v.w);
    *((uint4*)(g_w1r + (size_t)r * HH) + q) = u;
}

__global__ void prep_w2_kernel(const float* __restrict__ w2) {
    size_t idx = (size_t)blockIdx.x * 256 + threadIdx.x;  // float4 index
    float4 v = *((const float4*)w2 + idx);
    uint4 u;
    u.x = f2tf(v.x); u.y = f2tf(v.y); u.z = f2tf(v.z); u.w = f2tf(v.w);
    *((uint4*)g_w2r + idx) = u;
}

// ---------------- kernel 1: fused RMSNorm + gate + top4 + routing -------------
__global__ void norm_gate_kernel(const float* __restrict__ x,
                                 const float* __restrict__ scale,
                                 const float* __restrict__ gate_w,
                                 const float* __restrict__ gate_b) {
    int t = blockIdx.x;
    int tid = threadIdx.x;
    __shared__ float ts[HH];
    __shared__ float gv[NE];
    __shared__ float red[8];

    float4 v = *((const float4*)(x + (size_t)t * HH) + tid);
    float ss = v.x * v.x + v.y * v.y + v.z * v.z + v.w * v.w;
    #pragma unroll
    for (int o = 16; o; o >>= 1) ss += __shfl_xor_sync(0xffffffffu, ss, o);
    if ((tid & 31) == 0) red[tid >> 5] = ss;
    __syncthreads();
    if (tid < 8) {
        float s2 = red[tid];
        #pragma unroll
        for (int o = 4; o; o >>= 1) s2 += __shfl_xor_sync(0xffu, s2, o);
        if (tid == 0) red[0] = s2;
    }
    __syncthreads();
    float rms = rsqrtf(red[0] * (1.0f / HH) + EPSF);
    float4 sc = *((const float4*)scale + tid);
    float4 tv;
    tv.x = v.x * rms * sc.x; tv.y = v.y * rms * sc.y;
    tv.z = v.z * rms * sc.z; tv.w = v.w * rms * sc.w;
    *((float4*)ts + tid) = tv;
    uint4 u;
    u.x = f2tf(tv.x); u.y = f2tf(tv.y); u.z = f2tf(tv.z); u.w = f2tf(tv.w);
    *((uint4*)(g_t + (size_t)t * HH) + tid) = u;
    __syncthreads();

    int g = tid >> 4;
    int j = tid & 15;
    const float* wr = gate_w + g * HH;
    float sum = 0.f;
    for (int h = j; h < HH; h += 16) sum += ts[h] * wr[h];
    #pragma unroll
    for (int o = 8; o; o >>= 1) sum += __shfl_xor_sync(0xffffffffu, sum, o);
    if (j == 0) gv[g] = sum + gate_b[g];
    __syncthreads();

    if (tid == 0) {
        float vals[KTOP];
        int   idx[KTOP];
        bool  used[NE];
        #pragma unroll
        for (int e = 0; e < NE; e++) used[e] = false;
        #pragma unroll
        for (int k = 0; k < KTOP; k++) {
            float best = -INFINITY; int bi = 0;
            for (int e = 0; e < NE; e++)
                if (!used[e] && gv[e] > best) { best = gv[e]; bi = e; }
            used[bi] = true; vals[k] = best; idx[k] = bi;
        }
        float m = vals[0];
        float se = 0.f, w[KTOP];
        #pragma unroll
        for (int k = 0; k < KTOP; k++) { w[k] = __expf(vals[k] - m); se += w[k]; }
        float inv = 1.0f / se;
        #pragma unroll
        for (int k = 0; k < KTOP; k++) {
            int slot = t * KTOP + k;
            g_slot_w[slot] = w[k] * inv;
            int pos = atomicAdd(&g_expert_cnt[idx[k]], 1);
            g_expert_slots[idx[k] * TT + pos] = slot;
        }
    }
}

// ================= tf32 mma.sync GEMMs =========================================
// 128x128 block tile, 8 warps (4m x 2n), 32x64 warp tile, ldmatrix frags.
// BOTH operands pure cp.async from pre-rounded tf32 sources; 4-stage pipeline;
// 2 CTAs/SM (16 warps/SM) for latency hiding.

// ---------------- mlp1: GEMM1 (pre-gathered even w1 rows) + bias + swiglu -----
__global__ void __launch_bounds__(256, 2) mlp1_kernel(const float* __restrict__ b1) {
    int e = blockIdx.z;
    int cnt = g_expert_cnt[e];
    int mt = blockIdx.x;
    if (mt * BM >= cnt) return;
    int ntB = blockIdx.y * BN;

    extern __shared__ __align__(16) char dsm[];
    unsigned smb;
    asm("{ .reg .u64 t; cvta.to.shared.u64 t, %1; cvt.u32.u64 %0, t; }" : "=r"(smb) : "l"(dsm));
    __shared__ int slots[BM];

    int tid = threadIdx.x;
    if (tid < BM) {
        int idx = mt * BM + tid;
        slots[tid] = (idx < cnt) ? g_expert_slots[e * TT + idx] : -1;
    }
    __syncthreads();

    int lane = tid & 31, wid = tid >> 5;
    int wm = wid & 3, wn = wid >> 2;          // 4m x 2n warps, 32x64 tiles
    int grp = lane >> 2, tig = lane & 3;
    int rA = (lane & 7) + (((lane >> 3) & 1) << 3);
    int kA = (lane >> 4) << 2;
    int rB = (lane & 7) + ((lane >> 4) << 3);
    int kB = ((lane >> 3) & 1) << 2;
    unsigned aFrag = smb + (unsigned)(((wm * 32 + rA) * PAD + kA) * 4);
    unsigned bFrag = smb + B_REGION + (unsigned)(((wn * 64 + rB) * PAD + kB) * 4);

    // staging: each thread covers quad idx tid and tid+256
    int r0 = tid >> 2;               // 0..63
    int kq = (tid & 3) * 4;
    const float* w1e = g_w1r + (size_t)e * II * HH;
    const float* aptr[2];
    const float* bptr[2];
    #pragma unroll
    for (int i = 0; i < 2; i++) {
        int s = slots[r0 + 64 * i];
        aptr[i] = g_t + (size_t)((s >= 0) ? (s >> 2) : 0) * HH + kq;
        bptr[i] = w1e + (size_t)(ntB + r0 + 64 * i) * HH + kq;
    }
    unsigned aDst = smb + (unsigned)((r0 * PAD + kq) * 4);
    unsigned bDst = smb + B_REGION + (unsigned)((r0 * PAD + kq) * 4);

    float acc[2][8][4] = {};

    // prologue: stages 0..2
    #pragma unroll
    for (int c = 0; c < NSTG - 1; c++) {
        #pragma unroll
        for (int i = 0; i < 2; i++) {
            cp16(aDst + c * STG_A_BYTES + i * (64 * PAD * 4), aptr[i] + c * BK);
            cp16(bDst + c * STG_B_BYTES + i * (64 * PAD * 4), bptr[i] + c * BK);
        }
        CP_COMMIT();
    }

    const int NKT = HH / BK;   // 64
    #pragma unroll 2
    for (int kb = 0; kb < NKT; kb++) {
        int cur = kb & (NSTG - 1);
        CP_WAIT2();
        __syncthreads();
        int kf = kb + NSTG - 1;
        if (kf < NKT) {
            int st = kf & (NSTG - 1);
            #pragma unroll
            for (int i = 0; i < 2; i++) {
                cp16(aDst + st * STG_A_BYTES + i * (64 * PAD * 4), aptr[i] + kf * BK);
                cp16(bDst + st * STG_B_BYTES + i * (64 * PAD * 4), bptr[i] + kf * BK);
            }
        }
        CP_COMMIT();
        unsigned aOff = aFrag + (unsigned)(cur * STG_A_BYTES);
        unsigned bOff = bFrag + (unsigned)(cur * STG_B_BYTES);
        #pragma unroll
        for (int ks = 0; ks < 2; ks++) {
            unsigned afr[2][4], bfr[4][4];
            #pragma unroll
            for (int sm = 0; sm < 2; sm++)
                ldsm4(afr[sm], aOff + (unsigned)((sm * 16 * PAD + ks * 8) * 4));
            #pragma unroll
            for (int p = 0; p < 4; p++)
                ldsm4(bfr[p], bOff + (unsigned)((p * 16 * PAD + ks * 8) * 4));
            #pragma unroll
            for (int sm = 0; sm < 2; sm++)
                #pragma unroll
                for (int sn = 0; sn < 8; sn++)
                    mma_tf32(acc[sm][sn], afr[sm], &bfr[sn >> 1][(sn & 1) * 2]);
        }
    }

    const float* b1e = b1 + e * (2 * II);
    #pragma unroll
    for (int sm = 0; sm < 2; sm++) {
        int rbase = wm * 32 + sm * 16 + grp;
        #pragma unroll
        for (int half = 0; half < 2; half++) {
            int row = rbase + half * 8;
            int slot = slots[row];
            if (slot < 0) continue;
            float* srow = g_s + (size_t)slot * II;
            #pragma unroll
            for (int sn = 0; sn < 8; sn++) {
                int n = ntB + wn * 64 + sn * 8 + 2 * tig;
                #pragma unroll
                for (int cc = 0; cc < 2; cc++) {
                    float hsum = acc[sm][sn][half * 2 + cc] + b1e[2 * (n + cc)];
                    float gl = fminf(hsum, LIMITF);
                    float sig = 1.0f / (1.0f + __expf(-ALPHAF * gl));
                    srow[n + cc] = __uint_as_float(f2tf(gl * sig * (LIMITF + 1.0f)));
                }
            }
        }
    }
}

// ---------------- mlp2: GEMM2 + bias, scaled by routing weight ----------------
__global__ void __launch_bounds__(256, 2) mlp2_kernel(const float* __restrict__ b2) {
    int e = blockIdx.z;
    int cnt = g_expert_cnt[e];
    int mt = blockIdx.x;
    if (mt * BM >= cnt) return;
    int ntB = blockIdx.y * BN;

    extern __shared__ __align__(16) char dsm[];
    unsigned smb;
    asm("{ .reg .u64 t; cvta.to.shared.u64 t, %1; cvt.u32.u64 %0, t; }" : "=r"(smb) : "l"(dsm));
    __shared__ int slots[BM];

    int tid = threadIdx.x;
    if (tid < BM) {
        int idx = mt * BM + tid;
        slots[tid] = (idx < cnt) ? g_expert_slots[e * TT + idx] : -1;
    }
    __syncthreads();

    int lane = tid & 31, wid = tid >> 5;
    int wm = wid & 3, wn = wid >> 2;
    int grp = lane >> 2, tig = lane & 3;
    int rA = (lane & 7) + (((lane >> 3) & 1) << 3);
    int kA = (lane >> 4) << 2;
    int rB = (lane & 7) + ((lane >> 4) << 3);
    int kB = ((lane >> 3) & 1) << 2;
    unsigned aFrag = smb + (unsigned)(((wm * 32 + rA) * PAD + kA) * 4);
    unsigned bFrag = smb + B_REGION + (unsigned)(((wn * 64 + rB) * PAD + kB) * 4);

    int r0 = tid >> 2;
    int kq = (tid & 3) * 4;
    const float* w2e = g_w2r + (size_t)e * HH * II;
    const float* aptr[2];
    const float* bptr[2];
    #pragma unroll
    for (int i = 0; i < 2; i++) {
        int s = slots[r0 + 64 * i];
        aptr[i] = g_s + (size_t)((s >= 0) ? s : 0) * II + kq;
        bptr[i] = w2e + (size_t)(ntB + r0 + 64 * i) * II + kq;
    }
    unsigned aDst = smb + (unsigned)((r0 * PAD + kq) * 4);
    unsigned bDst = smb + B_REGION + (unsigned)((r0 * PAD + kq) * 4);

    float acc[2][8][4] = {};

    #pragma unroll
    for (int c = 0; c < NSTG - 1; c++) {
        #pragma unroll
        for (int i = 0; i < 2; i++) {
            cp16(aDst + c * STG_A_BYTES + i * (64 * PAD * 4), aptr[i] + c * BK);
            cp16(bDst + c * STG_B_BYTES + i * (64 * PAD * 4), bptr[i] + c * BK);
        }
        CP_COMMIT();
    }

    const int NKT = II / BK;
    #pragma unroll 2
    for (int kb = 0; kb < NKT; kb++) {
        int cur = kb & (NSTG - 1);
        CP_WAIT2();
        __syncthreads();
        int kf = kb + NSTG - 1;
        if (kf < NKT) {
            int st = kf & (NSTG - 1);
            #pragma unroll
            for (int i = 0; i < 2; i++) {
                cp16(aDst + st * STG_A_BYTES + i * (64 * PAD * 4), aptr[i] + kf * BK);
                cp16(bDst + st * STG_B_BYTES + i * (64 * PAD * 4), bptr[i] + kf * BK);
            }
        }
        CP_COMMIT();
        unsigned aOff = aFrag + (unsigned)(cur * STG_A_BYTES);
        unsigned bOff = bFrag + (unsigned)(cur * STG_B_BYTES);
        #pragma unroll
        for (int ks = 0; ks < 2; ks++) {
            unsigned afr[2][4], bfr[4][4];
            #pragma unroll
            for (int sm = 0; sm < 2; sm++)
                ldsm4(afr[sm], aOff + (unsigned)((sm * 16 * PAD + ks * 8) * 4));
            #pragma unroll
            for (int p = 0; p < 4; p++)
                ldsm4(bfr[p], bOff + (unsigned)((p * 16 * PAD + ks * 8) * 4));
            #pragma unroll
            for (int sm = 0; sm < 2; sm++)
                #pragma unroll
                for (int sn = 0; sn < 8; sn++)
                    mma_tf32(acc[sm][sn], afr[sm], &bfr[sn >> 1][(sn & 1) * 2]);
        }
    }

    const float* b2e = b2 + e * HH;
    #pragma unroll
    for (int sm = 0; sm < 2; sm++) {
        int rbase = wm * 32 + sm * 16 + grp;
        #pragma unroll
        for (int half = 0; half < 2; half++) {
            int row = rbase + half * 8;
            int slot = slots[row];
            if (slot < 0) continue;
            float rw = g_slot_w[slot];
            float* yrow = g_y + (size_t)slot * HH;
            #pragma unroll
            for (int sn = 0; sn < 8; sn++) {
                int n = ntB + wn * 64 + sn * 8 + 2 * tig;
                #pragma unroll
                for (int cc = 0; cc < 2; cc++)
                    yrow[n + cc] = (acc[sm][sn][half * 2 + cc] + b2e[n + cc]) * rw;
            }
        }
    }
}

// ---------------- finalize: out = x + sum_k y[t*4+k] --------------------------
__global__ void finalize_kernel(const float* __restrict__ x,
                                float* __restrict__ out) {
    int qi = blockIdx.x * 256 + threadIdx.x;
    int t = qi >> 8;
    int h4 = qi & 255;
    float4 v = *((const float4*)x + qi);
    const float4* yb = (const float4*)(g_y + (size_t)t * KTOP * HH) + h4;
    float4 a = yb[0], b = yb[256], c = yb[512], d = yb[768];
    v.x += a.x + b.x + c.x + d.x;
    v.y += a.y + b.y + c.y + d.y;
    v.z += a.z + b.z + c.z + d.z;
    v.w += a.w + b.w + c.w + d.w;
    *((float4*)out + qi) = v;
}

// ---------------- launcher -----------------------------------------------------
extern "C" void kernel_launch(void* const* d_in, const int* in_sizes, int n_in,
                              void* d_out, int out_size) {
    const float* x      = (const float*)d_in[0];
    const float* scale  = (const float*)d_in[1];
    const float* gate_w = (const float*)d_in[2];
    const float* gate_b = (const float*)d_in[3];
    const float* w1     = (const float*)d_in[4];
    const float* b1     = (const float*)d_in[5];
    const float* w2     = (const float*)d_in[6];
    const float* b2     = (const float*)d_in[7];
    float* out = (float*)d_out;

    cudaFuncSetAttribute(mlp1_kernel, cudaFuncAttributeMaxDynamicSharedMemorySize, SMEM_BYTES);
    cudaFuncSetAttribute(mlp2_kernel, cudaFuncAttributeMaxDynamicSharedMemorySize, SMEM_BYTES);

    zero_cnt_kernel<<<1, 32>>>();
    prep_w1_kernel<<<(NE * II * HH / 4) / 256, 256>>>(w1);
    prep_w2_kernel<<<(NE * HH * II / 4) / 256, 256>>>(w2);
    norm_gate_kernel<<<TT, 256>>>(x, scale, gate_w, gate_b);

    dim3 g1(TT / BM, II / BN, NE);    // (16, 8, 16)
    mlp1_kernel<<<g1, 256, SMEM_BYTES>>>(b1);

    dim3 g2(TT / BM, HH / BN, NE);
    mlp2_kernel<<<g2, 256, SMEM_BYTES>>>(b2);

    finalize_kernel<<<(TT * HH) / 1024, 256>>>(x, out);
}

// round 12
// speedup vs baseline: 1.0357x; 1.0140x over previous
#include <cuda_runtime.h>
#include <math.h>

#define TT 2048
#define HH 1024
#define II 1024
#define NE 16
#define KTOP 4
#define EPSF 1e-5f
#define ALPHAF 1.702f
#define LIMITF 7.0f

#define BM 128
#define BN 128
#define BK 16
#define PAD 20
#define NSTG 3
#define STG_BYTES (128 * PAD * 4)             // 10240 per operand per stage
#define B_REGION (NSTG * STG_BYTES)           // 30720
#define SMEM_BYTES (2 * NSTG * STG_BYTES)     // 61440

// ---------------- scratch (static device globals; no allocation) -------------
__device__ __align__(16) float g_t[TT * HH];            // tf32-rounded rmsnorm out
__device__ __align__(16) float g_s[TT * KTOP * II];     // tf32-rounded swiglu out
__device__ __align__(16) float g_y[TT * KTOP * HH];
__device__ float g_slot_w[TT * KTOP];
__device__ int   g_expert_cnt[NE];
__device__ int   g_expert_slots[NE * TT];

// ---------------- helpers ------------------------------------------------------
__device__ __forceinline__ unsigned f2tf(float f) {
    unsigned r;
    asm("cvt.rna.tf32.f32 %0, %1;" : "=r"(r) : "f"(f));
    return r;
}

__device__ __forceinline__ void mma_tf32(float* d, const unsigned* a, const unsigned* b) {
    asm volatile(
        "mma.sync.aligned.m16n8k8.row.col.f32.tf32.tf32.f32 "
        "{%0,%1,%2,%3}, {%4,%5,%6,%7}, {%8,%9}, {%0,%1,%2,%3};"
        : "+f"(d[0]), "+f"(d[1]), "+f"(d[2]), "+f"(d[3])
        : "r"(a[0]), "r"(a[1]), "r"(a[2]), "r"(a[3]), "r"(b[0]), "r"(b[1]));
}

__device__ __forceinline__ void ldsm4(unsigned* r, unsigned addr) {
    asm volatile("ldmatrix.sync.aligned.m8n8.x4.shared.b16 {%0,%1,%2,%3}, [%4];"
        : "=r"(r[0]), "=r"(r[1]), "=r"(r[2]), "=r"(r[3]) : "r"(addr));
}

__device__ __forceinline__ void cp16(unsigned dst, const void* src) {
    asm volatile("cp.async.cg.shared.global [%0], [%1], 16;" :: "r"(dst), "l"(src));
}
#define CP_COMMIT() asm volatile("cp.async.commit_group;")
#define CP_WAIT1()  asm volatile("cp.async.wait_group 1;")

// ---------------- kernel 0 -----------------------------------------------------
__global__ void zero_cnt_kernel() {
    if (threadIdx.x < NE) g_expert_cnt[threadIdx.x] = 0;
}

// ---------------- kernel 1: fused RMSNorm + gate + top4 + routing -------------
__global__ void norm_gate_kernel(const float* __restrict__ x,
                                 const float* __restrict__ scale,
                                 const float* __restrict__ gate_w,
                                 const float* __restrict__ gate_b) {
    int t = blockIdx.x;
    int tid = threadIdx.x;
    __shared__ float ts[HH];
    __shared__ float gv[NE];
    __shared__ float red[8];

    float4 v = *((const float4*)(x + (size_t)t * HH) + tid);
    float ss = v.x * v.x + v.y * v.y + v.z * v.z + v.w * v.w;
    #pragma unroll
    for (int o = 16; o; o >>= 1) ss += __shfl_xor_sync(0xffffffffu, ss, o);
    if ((tid & 31) == 0) red[tid >> 5] = ss;
    __syncthreads();
    if (tid < 8) {
        float s2 = red[tid];
        #pragma unroll
        for (int o = 4; o; o >>= 1) s2 += __shfl_xor_sync(0xffu, s2, o);
        if (tid == 0) red[0] = s2;
    }
    __syncthreads();
    float rms = rsqrtf(red[0] * (1.0f / HH) + EPSF);
    float4 sc = *((const float4*)scale + tid);
    float4 tv;
    tv.x = v.x * rms * sc.x; tv.y = v.y * rms * sc.y;
    tv.z = v.z * rms * sc.z; tv.w = v.w * rms * sc.w;
    *((float4*)ts + tid) = tv;
    uint4 u;
    u.x = f2tf(tv.x); u.y = f2tf(tv.y); u.z = f2tf(tv.z); u.w = f2tf(tv.w);
    *((uint4*)(g_t + (size_t)t * HH) + tid) = u;
    __syncthreads();

    int g = tid >> 4;
    int j = tid & 15;
    const float* wr = gate_w + g * HH;
    float sum = 0.f;
    for (int h = j; h < HH; h += 16) sum += ts[h] * wr[h];
    #pragma unroll
    for (int o = 8; o; o >>= 1) sum += __shfl_xor_sync(0xffffffffu, sum, o);
    if (j == 0) gv[g] = sum + gate_b[g];
    __syncthreads();

    if (tid == 0) {
        float vals[KTOP];
        int   idx[KTOP];
        bool  used[NE];
        #pragma unroll
        for (int e = 0; e < NE; e++) used[e] = false;
        #pragma unroll
        for (int k = 0; k < KTOP; k++) {
            float best = -INFINITY; int bi = 0;
            for (int e = 0; e < NE; e++)
                if (!used[e] && gv[e] > best) { best = gv[e]; bi = e; }
            used[bi] = true; vals[k] = best; idx[k] = bi;
        }
        float m = vals[0];
        float se = 0.f, w[KTOP];
        #pragma unroll
        for (int k = 0; k < KTOP; k++) { w[k] = __expf(vals[k] - m); se += w[k]; }
        float inv = 1.0f / se;
        #pragma unroll
        for (int k = 0; k < KTOP; k++) {
            int slot = t * KTOP + k;
            g_slot_w[slot] = w[k] * inv;
            int pos = atomicAdd(&g_expert_cnt[idx[k]], 1);
            g_expert_slots[idx[k] * TT + pos] = slot;
        }
    }
}

// ================= tf32 mma.sync GEMMs =========================================
// 128x128 block, 512 threads = 16 warps (4m x 4n), 32x32 warp tiles.
// A via cp.async from pre-rounded tf32; B via LDG->cvt.rna->STS, 3-stage
// pipeline (R8 schedule). 2 CTAs/SM -> 32 warps/SM; tensor pipe binding.

// ---------------- mlp1: GEMM1 (even w1 rows) + bias + swiglu ------------------
__global__ void __launch_bounds__(512, 2) mlp1_kernel(const float* __restrict__ w1,
                                                      const float* __restrict__ b1) {
    int e = blockIdx.z;
    int cnt = g_expert_cnt[e];
    int mt = blockIdx.x;
    if (mt * BM >= cnt) return;
    int ntB = blockIdx.y * BN;

    extern __shared__ __align__(16) char dsm[];
    unsigned smb;
    asm("{ .reg .u64 t; cvta.to.shared.u64 t, %1; cvt.u32.u64 %0, t; }" : "=r"(smb) : "l"(dsm));
    __shared__ int slots[BM];

    int tid = threadIdx.x;
    if (tid < BM) {
        int idx = mt * BM + tid;
        slots[tid] = (idx < cnt) ? g_expert_slots[e * TT + idx] : -1;
    }
    __syncthreads();

    int lane = tid & 31, wid = tid >> 5;
    int wm = wid & 3, wn = wid >> 2;          // 4m x 4n warps, 32x32 tiles
    int grp = lane >> 2, tig = lane & 3;
    int rA = (lane & 7) + (((lane >> 3) & 1) << 3);
    int kA = (lane >> 4) << 2;
    int rB = (lane & 7) + ((lane >> 4) << 3);
    int kB = ((lane >> 3) & 1) << 2;
    unsigned aFrag = smb + (unsigned)(((wm * 32 + rA) * PAD + kA) * 4);
    unsigned bFrag = smb + B_REGION + (unsigned)(((wn * 32 + rB) * PAD + kB) * 4);

    // staging: 512 threads, one quad each per operand per k-tile
    int r0 = tid >> 2;               // 0..127
    int kq = (tid & 3) * 4;
    const float* w1e = w1 + (size_t)e * (2 * II) * HH;
    int s0 = slots[r0];
    const float* aptr = g_t + (size_t)((s0 >= 0) ? (s0 >> 2) : 0) * HH + kq;
    const float* bptr = w1e + (size_t)(2 * (ntB + r0)) * HH + kq;
    unsigned aDst = smb + (unsigned)((r0 * PAD + kq) * 4);
    char*    bDst = dsm + B_REGION + (unsigned)((r0 * PAD + kq) * 4);

    float acc[2][4][4] = {};
    float4 bv;

    // prologue: B stage0 LDG+cvt+STS; A stage0/1 cp.async; B stage1 LDG
    {
        float4 b0 = *(const float4*)(bptr);
        uint4 u;
        u.x = f2tf(b0.x); u.y = f2tf(b0.y); u.z = f2tf(b0.z); u.w = f2tf(b0.w);
        *(uint4*)(bDst) = u;
    }
    cp16(aDst, aptr);
    CP_COMMIT();
    cp16(aDst + STG_BYTES, aptr + BK);
    CP_COMMIT();
    bv = *(const float4*)(bptr + BK);

    const int NKT = HH / BK;   // 64
    for (int kb = 0; kb < NKT; kb++) {
        int cur = kb % NSTG;
        CP_WAIT1();
        __syncthreads();
        if (kb + 1 < NKT) {                 // STS B stage kb+1
            int st = (kb + 1) % NSTG;
            uint4 u;
            u.x = f2tf(bv.x); u.y = f2tf(bv.y); u.z = f2tf(bv.z); u.w = f2tf(bv.w);
            *(uint4*)(bDst + st * STG_BYTES) = u;
        }
        if (kb + 2 < NKT) {                 // A cp.async stage kb+2
            int st = (kb + 2) % NSTG;
            cp16(aDst + (unsigned)(st * STG_BYTES), aptr + (kb + 2) * BK);
        }
        CP_COMMIT();
        if (kb + 2 < NKT)                   // B LDG stage kb+2
            bv = *(const float4*)(bptr + (kb + 2) * BK);

        unsigned aOff = aFrag + (unsigned)(cur * STG_BYTES);
        unsigned bOff = bFrag + (unsigned)(cur * STG_BYTES);
        #pragma unroll
        for (int ks = 0; ks < 2; ks++) {
            unsigned afr[2][4], bfr[2][4];
            #pragma unroll
            for (int sm = 0; sm < 2; sm++)
                ldsm4(afr[sm], aOff + (unsigned)((sm * 16 * PAD + ks * 8) * 4));
            #pragma unroll
            for (int p = 0; p < 2; p++)
                ldsm4(bfr[p], bOff + (unsigned)((p * 16 * PAD + ks * 8) * 4));
            #pragma unroll
            for (int sm = 0; sm < 2; sm++)
                #pragma unroll
                for (int sn = 0; sn < 4; sn++)
                    mma_tf32(acc[sm][sn], afr[sm], &bfr[sn >> 1][(sn & 1) * 2]);
        }
    }

    const float* b1e = b1 + e * (2 * II);
    #pragma unroll
    for (int sm = 0; sm < 2; sm++) {
        int rbase = wm * 32 + sm * 16 + grp;
        #pragma unroll
        for (int half = 0; half < 2; half++) {
            int row = rbase + half * 8;
            int slot = slots[row];
            if (slot < 0) continue;
            float* srow = g_s + (size_t)slot * II;
            #pragma unroll
            for (int sn = 0; sn < 4; sn++) {
                int n = ntB + wn * 32 + sn * 8 + 2 * tig;
                #pragma unroll
                for (int cc = 0; cc < 2; cc++) {
                    float hsum = acc[sm][sn][half * 2 + cc] + b1e[2 * (n + cc)];
                    float gl = fminf(hsum, LIMITF);
                    float sig = 1.0f / (1.0f + __expf(-ALPHAF * gl));
                    srow[n + cc] = __uint_as_float(f2tf(gl * sig * (LIMITF + 1.0f)));
                }
            }
        }
    }
}

// ---------------- mlp2: GEMM2 + bias, scaled by routing weight ----------------
__global__ void __launch_bounds__(512, 2) mlp2_kernel(const float* __restrict__ w2,
                                                      const float* __restrict__ b2) {
    int e = blockIdx.z;
    int cnt = g_expert_cnt[e];
    int mt = blockIdx.x;
    if (mt * BM >= cnt) return;
    int ntB = blockIdx.y * BN;

    extern __shared__ __align__(16) char dsm[];
    unsigned smb;
    asm("{ .reg .u64 t; cvta.to.shared.u64 t, %1; cvt.u32.u64 %0, t; }" : "=r"(smb) : "l"(dsm));
    __shared__ int slots[BM];

    int tid = threadIdx.x;
    if (tid < BM) {
        int idx = mt * BM + tid;
        slots[tid] = (idx < cnt) ? g_expert_slots[e * TT + idx] : -1;
    }
    __syncthreads();

    int lane = tid & 31, wid = tid >> 5;
    int wm = wid & 3, wn = wid >> 2;
    int grp = lane >> 2, tig = lane & 3;
    int rA = (lane & 7) + (((lane >> 3) & 1) << 3);
    int kA = (lane >> 4) << 2;
    int rB = (lane & 7) + ((lane >> 4) << 3);
    int kB = ((lane >> 3) & 1) << 2;
    unsigned aFrag = smb + (unsigned)(((wm * 32 + rA) * PAD + kA) * 4);
    unsigned bFrag = smb + B_REGION + (unsigned)(((wn * 32 + rB) * PAD + kB) * 4);

    int r0 = tid >> 2;
    int kq = (tid & 3) * 4;
    const float* w2e = w2 + (size_t)e * HH * II;
    int s0 = slots[r0];
    const float* aptr = g_s + (size_t)((s0 >= 0) ? s0 : 0) * II + kq;
    const float* bptr = w2e + (size_t)(ntB + r0) * II + kq;
    unsigned aDst = smb + (unsigned)((r0 * PAD + kq) * 4);
    char*    bDst = dsm + B_REGION + (unsigned)((r0 * PAD + kq) * 4);

    float acc[2][4][4] = {};
    float4 bv;

    {
        float4 b0 = *(const float4*)(bptr);
        uint4 u;
        u.x = f2tf(b0.x); u.y = f2tf(b0.y); u.z = f2tf(b0.z); u.w = f2tf(b0.w);
        *(uint4*)(bDst) = u;
    }
    cp16(aDst, aptr);
    CP_COMMIT();
    cp16(aDst + STG_BYTES, aptr + BK);
    CP_COMMIT();
    bv = *(const float4*)(bptr + BK);

    const int NKT = II / BK;
    for (int kb = 0; kb < NKT; kb++) {
        int cur = kb % NSTG;
        CP_WAIT1();
        __syncthreads();
        if (kb + 1 < NKT) {
            int st = (kb + 1) % NSTG;
            uint4 u;
            u.x = f2tf(bv.x); u.y = f2tf(bv.y); u.z = f2tf(bv.z); u.w = f2tf(bv.w);
            *(uint4*)(bDst + st * STG_BYTES) = u;
        }
        if (kb + 2 < NKT) {
            int st = (kb + 2) % NSTG;
            cp16(aDst + (unsigned)(st * STG_BYTES), aptr + (kb + 2) * BK);
        }
        CP_COMMIT();
        if (kb + 2 < NKT)
            bv = *(const float4*)(bptr + (kb + 2) * BK);

        unsigned aOff = aFrag + (unsigned)(cur * STG_BYTES);
        unsigned bOff = bFrag + (unsigned)(cur * STG_BYTES);
        #pragma unroll
        for (int ks = 0; ks < 2; ks++) {
            unsigned afr[2][4], bfr[2][4];
            #pragma unroll
            for (int sm = 0; sm < 2; sm++)
                ldsm4(afr[sm], aOff + (unsigned)((sm * 16 * PAD + ks * 8) * 4));
            #pragma unroll
            for (int p = 0; p < 2; p++)
                ldsm4(bfr[p], bOff + (unsigned)((p * 16 * PAD + ks * 8) * 4));
            #pragma unroll
            for (int sm = 0; sm < 2; sm++)
                #pragma unroll
                for (int sn = 0; sn < 4; sn++)
                    mma_tf32(acc[sm][sn], afr[sm], &bfr[sn >> 1][(sn & 1) * 2]);
        }
    }

    const float* b2e = b2 + e * HH;
    #pragma unroll
    for (int sm = 0; sm < 2; sm++) {
        int rbase = wm * 32 + sm * 16 + grp;
        #pragma unroll
        for (int half = 0; half < 2; half++) {
            int row = rbase + half * 8;
            int slot = slots[row];
            if (slot < 0) continue;
            float rw = g_slot_w[slot];
            float* yrow = g_y + (size_t)slot * HH;
            #pragma unroll
            for (int sn = 0; sn < 4; sn++) {
                int n = ntB + wn * 32 + sn * 8 + 2 * tig;
                #pragma unroll
                for (int cc = 0; cc < 2; cc++)
                    yrow[n + cc] = (acc[sm][sn][half * 2 + cc] + b2e[n + cc]) * rw;
            }
        }
    }
}

// ---------------- finalize: out = x + sum_k y[t*4+k] --------------------------
__global__ void finalize_kernel(const float* __restrict__ x,
                                float* __restrict__ out) {
    int qi = blockIdx.x * 256 + threadIdx.x;
    int t = qi >> 8;
    int h4 = qi & 255;
    float4 v = *((const float4*)x + qi);
    const float4* yb = (const float4*)(g_y + (size_t)t * KTOP * HH) + h4;
    float4 a = yb[0], b = yb[256], c = yb[512], d = yb[768];
    v.x += a.x + b.x + c.x + d.x;
    v.y += a.y + b.y + c.y + d.y;
    v.z += a.z + b.z + c.z + d.z;
    v.w += a.w + b.w + c.w + d.w;
    *((float4*)out + qi) = v;
}

// ---------------- launcher -----------------------------------------------------
extern "C" void kernel_launch(void* const* d_in, const int* in_sizes, int n_in,
                              void* d_out, int out_size) {
    const float* x      = (const float*)d_in[0];
    const float* scale  = (const float*)d_in[1];
    const float* gate_w = (const float*)d_in[2];
    const float* gate_b = (const float*)d_in[3];
    const float* w1     = (const float*)d_in[4];
    const float* b1     = (const float*)d_in[5];
    const float* w2     = (const float*)d_in[6];
    const float* b2     = (const float*)d_in[7];
    float* out = (float*)d_out;

    cudaFuncSetAttribute(mlp1_kernel, cudaFuncAttributeMaxDynamicSharedMemorySize, SMEM_BYTES);
    cudaFuncSetAttribute(mlp2_kernel, cudaFuncAttributeMaxDynamicSharedMemorySize, SMEM_BYTES);

    zero_cnt_kernel<<<1, 32>>>();
    norm_gate_kernel<<<TT, 256>>>(x, scale, gate_w, gate_b);

    dim3 g1(TT / BM, II / BN, NE);    // (16, 8, 16)
    mlp1_kernel<<<g1, 512, SMEM_BYTES>>>(w1, b1);

    dim3 g2(TT / BM, HH / BN, NE);
    mlp2_kernel<<<g2, 512, SMEM_BYTES>>>(w2, b2);

    finalize_kernel<<<(TT * HH) / 1024, 256>>>(x, out);
}